// round 13
// baseline (speedup 1.0000x reference)
#include <cuda_runtime.h>
#include <cuda_fp16.h>
#include <cstdint>

// ============================================================
// Fused GRUCell, sm_103 base-PTX (ldmatrix + mma.sync.m16n8k16).
// R10 permuted-layout kernel + liveness-minimizing gate order:
//   z-GEMMs -> z packed fp16 (zc dies) -> r-GEMMs -> rhf (rc dies)
//   -> n-GEMMs -> n packed fp16 (nc dies) -> epilogue.
// Peak live set ~210 regs -> 288-thread CTAs (9 warps, 224-reg
// natural cap, no spills).
//   r = sig(x@Wir + hx@Whr + br); z = sig(x@Wiz + hx@Whz + bz)
//   n = tanh(x@Win + (r*hx)@Whn + bn); h = hx + z*(n - hx)
// B = 1048576, H = 64. M = 32 rows per warp per iteration.
// ============================================================

#define DEV __device__ __forceinline__

static constexpr int NSLAB = 1048576 / 32;       // 32768 slabs of 32 rows
static constexpr int NW    = 9;                  // warps per CTA

// ---- dynamic SMEM layout (bytes) ----
static constexpr int OFF_W    = 0;               // 6 x [64x64] f16 SW128 rows = 49152
static constexpr int OFF_BIAS = 49152;           // 3 x 64 fp32 = 768
static constexpr int SMEM_SZ  = 50176;

DEV uint32_t sw(uint32_t o) { return o ^ ((o >> 3) & 0x70); }

DEV uint32_t s2u(const void* p) {
    uint32_t a;
    asm("{ .reg .u64 t; cvta.to.shared.u64 t, %1; cvt.u32.u64 %0, t; }" : "=r"(a) : "l"(p));
    return a;
}

DEV void pf_l2(const void* p) {
    asm volatile("prefetch.global.L2 [%0];" :: "l"(p));
}

DEV void ldsm4t(uint32_t& d0, uint32_t& d1, uint32_t& d2, uint32_t& d3, uint32_t a) {
    asm volatile("ldmatrix.sync.aligned.m8n8.x4.trans.shared.b16 {%0,%1,%2,%3}, [%4];"
                 : "=r"(d0), "=r"(d1), "=r"(d2), "=r"(d3) : "r"(a));
}

DEV void mma4(float* c, const uint32_t* a, uint32_t b0, uint32_t b1) {
    asm volatile(
        "mma.sync.aligned.m16n8k16.row.col.f32.f16.f16.f32 "
        "{%0,%1,%2,%3}, {%4,%5,%6,%7}, {%8,%9}, {%0,%1,%2,%3};"
        : "+f"(c[0]), "+f"(c[1]), "+f"(c[2]), "+f"(c[3])
        : "r"(a[0]), "r"(a[1]), "r"(a[2]), "r"(a[3]), "r"(b0), "r"(b1));
}

// single-MUFU activations
DEV float tanh_ap(float x) {
    float r;
    asm("tanh.approx.f32 %0, %1;" : "=f"(r) : "f"(x));
    return r;
}
DEV float sigm(float x) { return fmaf(0.5f, tanh_ap(0.5f * x), 0.5f); }

DEV uint32_t packh2(float a, float b) {
    __half2 h = __floats2half2_rn(a, b);
    return *(uint32_t*)&h;
}

// GEMM accumulate: acc[2][8][4] += A(32x64 reg frags) @ W(64x64 f16 smem)
DEV void gemm2(float acc[2][8][4], const uint32_t af[2][4][4], uint32_t wbase, int laneB) {
    #pragma unroll
    for (int kb = 0; kb < 4; kb++) {
        #pragma unroll
        for (int nbp = 0; nbp < 4; nbp++) {
            uint32_t b0, b1, b2, b3;
            ldsm4t(b0, b1, b2, b3, wbase + sw((uint32_t)(laneB + kb * 2048 + nbp * 32)));
            #pragma unroll
            for (int mb = 0; mb < 2; mb++) {
                mma4(acc[mb][2 * nbp],     af[mb][kb], b0, b1);
                mma4(acc[mb][2 * nbp + 1], af[mb][kb], b2, b3);
            }
        }
    }
}

__global__ void __launch_bounds__(32 * NW, 1) gru_kernel(
    const float* __restrict__ x,    const float* __restrict__ hx,
    const float* __restrict__ w_ir, const float* __restrict__ w_hr,
    const float* __restrict__ w_iz, const float* __restrict__ w_hz,
    const float* __restrict__ w_in, const float* __restrict__ w_hn,
    const float* __restrict__ b_r,  const float* __restrict__ b_z,
    const float* __restrict__ b_n,  float* __restrict__ out)
{
    extern __shared__ char sm[];
    const uint32_t SB = s2u(sm);
    const int tid  = threadIdx.x;
    const int lane = tid & 31;
    const int wid  = tid >> 5;

    // ---- one-time: weights -> f16 SMEM, K-rows and N-cols permuted ----
    // K row perm (per 16-block):  krow(k) = 2*((k>>2)&3) + (k&1) + ((k&2)<<2)
    // N col perm sigma^-1 (per 16-block): pos(n) = ((n&2)<<2) | ((n>>1)&6) | (n&1)
    {
        const float* ws[6] = {w_ir, w_hr, w_iz, w_hz, w_in, w_hn};
        #pragma unroll 1
        for (int g = 0; g < 6; g++) {
            const float* w = ws[g];
            for (int i = tid; i < 4096; i += 32 * NW) {
                int k = i >> 6, n = i & 63;
                int krow = (k & 48) | (2 * ((k >> 2) & 3) + (k & 1) + ((k & 2) << 2));
                int ncol = (n & 48) | ((n & 2) << 2) | ((n >> 1) & 6) | (n & 1);
                *(__half*)(sm + OFF_W + g * 8192 + sw((uint32_t)(krow * 128 + ncol * 2))) =
                    __float2half_rn(w[i]);
            }
        }
        if (tid < 64) {
            // bias position j holds b[sigma(j)]
            int m = ((tid >> 4) << 4) | ((tid & 6) << 1) | (((tid >> 3) & 1) << 1) | (tid & 1);
            float* bs = (float*)(sm + OFF_BIAS);
            bs[tid]       = b_r[m];
            bs[64 + tid]  = b_z[m];
            bs[128 + tid] = b_n[m];
        }
    }
    __syncthreads();   // only CTA-wide barrier in the kernel

    const int laneB = (lane & 15) * 128 + ((lane >> 4) << 4);  // ldmatrix B lane offset
    const int q2    = (lane & 3) * 2;
    const int t4    = (lane & 3) * 4;
    const int grow  = lane >> 2;

    const long stride = (long)NW * gridDim.x;

    for (long g = (long)blockIdx.x * NW + wid; g < NSLAB; g += stride) {
        // ---- L2 prefetch of next slab ----
        {
            const long gp = g + stride;
            if (gp < NSLAB) {
                const char* px = (const char*)(x  + (size_t)gp * 2048) + lane * 256;
                const char* ph = (const char*)(hx + (size_t)gp * 2048) + lane * 256;
                pf_l2(px); pf_l2(px + 128);
                pf_l2(ph); pf_l2(ph + 128);
            }
        }

        // ---- A-fragments via LDG.128 (permuted K space) ----
        uint32_t xf[2][4][4], hf[2][4][4];
        {
            const float* xb = x  + (size_t)g * 2048;   // 32 rows x 64
            const float* hb = hx + (size_t)g * 2048;
            #pragma unroll
            for (int mb = 0; mb < 2; mb++) {
                const float* xr = xb + (mb * 16 + grow) * 64 + t4;
                const float* hr = hb + (mb * 16 + grow) * 64 + t4;
                #pragma unroll
                for (int kb = 0; kb < 4; kb++) {
                    float4 q0 = *(const float4*)(xr + kb * 16);
                    float4 q8 = *(const float4*)(xr + kb * 16 + 512);   // +8 rows
                    xf[mb][kb][0] = packh2(q0.x, q0.y);
                    xf[mb][kb][2] = packh2(q0.z, q0.w);
                    xf[mb][kb][1] = packh2(q8.x, q8.y);
                    xf[mb][kb][3] = packh2(q8.z, q8.w);
                    float4 p0 = *(const float4*)(hr + kb * 16);
                    float4 p8 = *(const float4*)(hr + kb * 16 + 512);
                    hf[mb][kb][0] = packh2(p0.x, p0.y);
                    hf[mb][kb][2] = packh2(p0.z, p0.w);
                    hf[mb][kb][1] = packh2(p8.x, p8.y);
                    hf[mb][kb][3] = packh2(p8.z, p8.w);
                }
            }
        }

        // ---- z = sig(x@Wiz + hx@Whz + bz) first; pack to fp16 (zc dies) ----
        uint32_t zt[2][8][2];
        {
            float zc[2][8][4];
            #pragma unroll
            for (int nb = 0; nb < 8; nb++) {
                float2 bz = *(float2*)(sm + OFF_BIAS + 256 + (nb * 8 + q2) * 4);
                #pragma unroll
                for (int mb = 0; mb < 2; mb++) {
                    zc[mb][nb][0] = bz.x; zc[mb][nb][1] = bz.y;
                    zc[mb][nb][2] = bz.x; zc[mb][nb][3] = bz.y;
                }
            }
            gemm2(zc, xf, SB + OFF_W + 2 * 8192, laneB);
            gemm2(zc, hf, SB + OFF_W + 3 * 8192, laneB);
            #pragma unroll
            for (int mb = 0; mb < 2; mb++) {
                #pragma unroll
                for (int nb = 0; nb < 8; nb++) {
                    const float* zz = zc[mb][nb];
                    zt[mb][nb][0] = packh2(sigm(zz[0]), sigm(zz[1]));  // row grow
                    zt[mb][nb][1] = packh2(sigm(zz[2]), sigm(zz[3]));  // row grow+8
                }
            }
        }

        // ---- r = sig(x@Wir + hx@Whr + br) -> rhf = r*hx fp16 (rc dies) ----
        uint32_t rhf[2][4][4];
        {
            float rc[2][8][4];
            #pragma unroll
            for (int nb = 0; nb < 8; nb++) {
                float2 br = *(float2*)(sm + OFF_BIAS + (nb * 8 + q2) * 4);
                #pragma unroll
                for (int mb = 0; mb < 2; mb++) {
                    rc[mb][nb][0] = br.x; rc[mb][nb][1] = br.y;
                    rc[mb][nb][2] = br.x; rc[mb][nb][3] = br.y;
                }
            }
            gemm2(rc, xf, SB + OFF_W,            laneB);
            gemm2(rc, hf, SB + OFF_W + 1 * 8192, laneB);
            #pragma unroll
            for (int mb = 0; mb < 2; mb++) {
                #pragma unroll
                for (int kb = 0; kb < 4; kb++) {
                    const float* ce = rc[mb][2 * kb];
                    const float* co = rc[mb][2 * kb + 1];
                    __half2 s0 = __floats2half2_rn(sigm(ce[0]), sigm(ce[1]));
                    __half2 s1 = __floats2half2_rn(sigm(ce[2]), sigm(ce[3]));
                    __half2 s2 = __floats2half2_rn(sigm(co[0]), sigm(co[1]));
                    __half2 s3 = __floats2half2_rn(sigm(co[2]), sigm(co[3]));
                    __half2 m0 = __hmul2(s0, *(const __half2*)&hf[mb][kb][0]);
                    __half2 m1 = __hmul2(s1, *(const __half2*)&hf[mb][kb][1]);
                    __half2 m2 = __hmul2(s2, *(const __half2*)&hf[mb][kb][2]);
                    __half2 m3 = __hmul2(s3, *(const __half2*)&hf[mb][kb][3]);
                    rhf[mb][kb][0] = *(uint32_t*)&m0;
                    rhf[mb][kb][1] = *(uint32_t*)&m1;
                    rhf[mb][kb][2] = *(uint32_t*)&m2;
                    rhf[mb][kb][3] = *(uint32_t*)&m3;
                }
            }
        }

        // ---- n = x@Win + rh@Whn + bn; pack tanh(n) fp16 (nc dies) ----
        uint32_t nt[2][8][2];
        {
            float nc[2][8][4];
            #pragma unroll
            for (int nb = 0; nb < 8; nb++) {
                float2 bn = *(float2*)(sm + OFF_BIAS + 512 + (nb * 8 + q2) * 4);
                #pragma unroll
                for (int mb = 0; mb < 2; mb++) {
                    nc[mb][nb][0] = bn.x; nc[mb][nb][1] = bn.y;
                    nc[mb][nb][2] = bn.x; nc[mb][nb][3] = bn.y;
                }
            }
            gemm2(nc, xf,  SB + OFF_W + 4 * 8192, laneB);
            gemm2(nc, rhf, SB + OFF_W + 5 * 8192, laneB);
            #pragma unroll
            for (int mb = 0; mb < 2; mb++) {
                #pragma unroll
                for (int nb = 0; nb < 8; nb++) {
                    const float* nn = nc[mb][nb];
                    nt[mb][nb][0] = packh2(tanh_ap(nn[0]), tanh_ap(nn[1]));  // row grow
                    nt[mb][nb][1] = packh2(tanh_ap(nn[2]), tanh_ap(nn[3])); // row grow+8
                }
            }
        }

        // ---- epilogue: h = hx + z*(n - hx); z,n fp16; hx from hf; STG.128 ----
        #pragma unroll
        for (int mb = 0; mb < 2; mb++) {
            const long rg = g * 32 + mb * 16 + grow;
            #pragma unroll
            for (int kb = 0; kb < 4; kb++) {
                float2 h01 = __half22float2(*(const __half2*)&hf[mb][kb][0]); // row grow
                float2 h23 = __half22float2(*(const __half2*)&hf[mb][kb][2]);
                float2 g01 = __half22float2(*(const __half2*)&hf[mb][kb][1]); // row grow+8
                float2 g23 = __half22float2(*(const __half2*)&hf[mb][kb][3]);
                float2 ze0 = __half22float2(*(const __half2*)&zt[mb][2 * kb][0]);
                float2 zo0 = __half22float2(*(const __half2*)&zt[mb][2 * kb + 1][0]);
                float2 ze8 = __half22float2(*(const __half2*)&zt[mb][2 * kb][1]);
                float2 zo8 = __half22float2(*(const __half2*)&zt[mb][2 * kb + 1][1]);
                float2 ne0 = __half22float2(*(const __half2*)&nt[mb][2 * kb][0]);
                float2 no0 = __half22float2(*(const __half2*)&nt[mb][2 * kb + 1][0]);
                float2 ne8 = __half22float2(*(const __half2*)&nt[mb][2 * kb][1]);
                float2 no8 = __half22float2(*(const __half2*)&nt[mb][2 * kb + 1][1]);
                float4 o0, o8;
                o0.x = fmaf(ze0.x, ne0.x - h01.x, h01.x);
                o0.y = fmaf(ze0.y, ne0.y - h01.y, h01.y);
                o0.z = fmaf(zo0.x, no0.x - h23.x, h23.x);
                o0.w = fmaf(zo0.y, no0.y - h23.y, h23.y);
                o8.x = fmaf(ze8.x, ne8.x - g01.x, g01.x);
                o8.y = fmaf(ze8.y, ne8.y - g01.y, g01.y);
                o8.z = fmaf(zo8.x, no8.x - g23.x, g23.x);
                o8.w = fmaf(zo8.y, no8.y - g23.y, g23.y);
                *(float4*)(out + rg * 64 + kb * 16 + t4)       = o0;
                *(float4*)(out + (rg + 8) * 64 + kb * 16 + t4) = o8;
            }
        }
    }
}

extern "C" void kernel_launch(void* const* d_in, const int* in_sizes, int n_in,
                              void* d_out, int out_size) {
    int sms = 0;
    cudaDeviceGetAttribute(&sms, cudaDevAttrMultiProcessorCount, 0);
    if (sms <= 0) sms = 148;
    cudaFuncSetAttribute(gru_kernel, cudaFuncAttributeMaxDynamicSharedMemorySize, SMEM_SZ);
    gru_kernel<<<sms, 32 * NW, SMEM_SZ>>>(
        (const float*)d_in[0], (const float*)d_in[1],
        (const float*)d_in[2], (const float*)d_in[3],
        (const float*)d_in[4], (const float*)d_in[5],
        (const float*)d_in[6], (const float*)d_in[7],
        (const float*)d_in[8], (const float*)d_in[9],
        (const float*)d_in[10], (float*)d_out);
}

// round 14
// speedup vs baseline: 1.5794x; 1.5794x over previous
#include <cuda_runtime.h>
#include <cuda_fp16.h>
#include <cstdint>

// ============================================================
// Fused GRUCell, sm_103 base-PTX (ldmatrix + mma.sync.m16n8k16).
// R10 permuted-layout kernel + explicitly software-pipelined
// B-fragment loads: each gate's 32 (kb,nbp) MMA steps run with a
// 2-deep register double-buffer of ldmatrix.trans results, so the
// next B load issues before the current MMA group (hoist that
// ptxas won't do at 255 regs). All validated R10 math unchanged.
//   r = sig(x@Wir + hx@Whr + br); z = sig(x@Wiz + hx@Whz + bz)
//   n = tanh(x@Win + (r*hx)@Whn + bn); h = hx + z*(n - hx)
// B = 1048576, H = 64. M = 32 rows per warp per iteration.
// ============================================================

#define DEV __device__ __forceinline__

static constexpr int NSLAB = 1048576 / 32;       // 32768 slabs of 32 rows

// ---- dynamic SMEM layout (bytes) ----
static constexpr int OFF_W    = 0;               // 6 x [64x64] f16 SW128 rows = 49152
static constexpr int OFF_BIAS = 49152;           // 3 x 64 fp32 = 768
static constexpr int SMEM_SZ  = 50176;

DEV uint32_t sw(uint32_t o) { return o ^ ((o >> 3) & 0x70); }

DEV uint32_t s2u(const void* p) {
    uint32_t a;
    asm("{ .reg .u64 t; cvta.to.shared.u64 t, %1; cvt.u32.u64 %0, t; }" : "=r"(a) : "l"(p));
    return a;
}

DEV void pf_l2(const void* p) {
    asm volatile("prefetch.global.L2 [%0];" :: "l"(p));
}

DEV void ldsm4t(uint32_t& d0, uint32_t& d1, uint32_t& d2, uint32_t& d3, uint32_t a) {
    asm volatile("ldmatrix.sync.aligned.m8n8.x4.trans.shared.b16 {%0,%1,%2,%3}, [%4];"
                 : "=r"(d0), "=r"(d1), "=r"(d2), "=r"(d3) : "r"(a));
}

DEV void mma4(float* c, const uint32_t* a, uint32_t b0, uint32_t b1) {
    asm volatile(
        "mma.sync.aligned.m16n8k16.row.col.f32.f16.f16.f32 "
        "{%0,%1,%2,%3}, {%4,%5,%6,%7}, {%8,%9}, {%0,%1,%2,%3};"
        : "+f"(c[0]), "+f"(c[1]), "+f"(c[2]), "+f"(c[3])
        : "r"(a[0]), "r"(a[1]), "r"(a[2]), "r"(a[3]), "r"(b0), "r"(b1));
}

// single-MUFU activations
DEV float tanh_ap(float x) {
    float r;
    asm("tanh.approx.f32 %0, %1;" : "=f"(r) : "f"(x));
    return r;
}
DEV float sigm(float x) { return fmaf(0.5f, tanh_ap(0.5f * x), 0.5f); }

DEV uint32_t packh2(float a, float b) {
    __half2 h = __floats2half2_rn(a, b);
    return *(uint32_t*)&h;
}

// B-fragment smem address for step i (kb = i>>2, nbp = i&3)
DEV uint32_t baddr(uint32_t wb, int i, int laneB) {
    return wb + sw((uint32_t)(laneB + (i >> 2) * 2048 + (i & 3) * 32));
}

// One gate: acc += A0(32x64) @ W0 + A1(32x64) @ W1, with B-fragment
// loads software-pipelined (next ldsm issued before current MMA group).
DEV void gemm_gate(float acc[2][8][4],
                   const uint32_t af0[2][4][4], const uint32_t af1[2][4][4],
                   uint32_t wb0, uint32_t wb1, int laneB) {
    uint32_t b0[4], b1[4];
    ldsm4t(b0[0], b0[1], b0[2], b0[3], baddr(wb0, 0, laneB));
    #pragma unroll
    for (int i = 0; i < 16; i++) {
        uint32_t* bc = (i & 1) ? b1 : b0;
        uint32_t* bn = (i & 1) ? b0 : b1;
        if (i < 15) ldsm4t(bn[0], bn[1], bn[2], bn[3], baddr(wb0, i + 1, laneB));
        else        ldsm4t(bn[0], bn[1], bn[2], bn[3], baddr(wb1, 0, laneB));
        const int kb = i >> 2, nbp = i & 3;
        #pragma unroll
        for (int mb = 0; mb < 2; mb++) {
            mma4(acc[mb][2 * nbp],     af0[mb][kb], bc[0], bc[1]);
            mma4(acc[mb][2 * nbp + 1], af0[mb][kb], bc[2], bc[3]);
        }
    }
    #pragma unroll
    for (int i = 0; i < 16; i++) {
        uint32_t* bc = (i & 1) ? b1 : b0;
        uint32_t* bn = (i & 1) ? b0 : b1;
        if (i < 15) ldsm4t(bn[0], bn[1], bn[2], bn[3], baddr(wb1, i + 1, laneB));
        const int kb = i >> 2, nbp = i & 3;
        #pragma unroll
        for (int mb = 0; mb < 2; mb++) {
            mma4(acc[mb][2 * nbp],     af1[mb][kb], bc[0], bc[1]);
            mma4(acc[mb][2 * nbp + 1], af1[mb][kb], bc[2], bc[3]);
        }
    }
}

__global__ void __launch_bounds__(256, 1) gru_kernel(
    const float* __restrict__ x,    const float* __restrict__ hx,
    const float* __restrict__ w_ir, const float* __restrict__ w_hr,
    const float* __restrict__ w_iz, const float* __restrict__ w_hz,
    const float* __restrict__ w_in, const float* __restrict__ w_hn,
    const float* __restrict__ b_r,  const float* __restrict__ b_z,
    const float* __restrict__ b_n,  float* __restrict__ out)
{
    extern __shared__ char sm[];
    const uint32_t SB = s2u(sm);
    const int tid  = threadIdx.x;
    const int lane = tid & 31;
    const int wid  = tid >> 5;

    // ---- one-time: weights -> f16 SMEM, K-rows and N-cols permuted ----
    // K row perm (per 16-block):  krow(k) = 2*((k>>2)&3) + (k&1) + ((k&2)<<2)
    // N col perm sigma^-1 (per 16-block): pos(n) = ((n&2)<<2) | ((n>>1)&6) | (n&1)
    {
        const float* ws[6] = {w_ir, w_hr, w_iz, w_hz, w_in, w_hn};
        #pragma unroll 1
        for (int g = 0; g < 6; g++) {
            const float* w = ws[g];
            for (int i = tid; i < 4096; i += 256) {
                int k = i >> 6, n = i & 63;
                int krow = (k & 48) | (2 * ((k >> 2) & 3) + (k & 1) + ((k & 2) << 2));
                int ncol = (n & 48) | ((n & 2) << 2) | ((n >> 1) & 6) | (n & 1);
                *(__half*)(sm + OFF_W + g * 8192 + sw((uint32_t)(krow * 128 + ncol * 2))) =
                    __float2half_rn(w[i]);
            }
        }
        if (tid < 64) {
            // bias position j holds b[sigma(j)]
            int m = ((tid >> 4) << 4) | ((tid & 6) << 1) | (((tid >> 3) & 1) << 1) | (tid & 1);
            float* bs = (float*)(sm + OFF_BIAS);
            bs[tid]       = b_r[m];
            bs[64 + tid]  = b_z[m];
            bs[128 + tid] = b_n[m];
        }
    }
    __syncthreads();   // only CTA-wide barrier in the kernel

    const int laneB = (lane & 15) * 128 + ((lane >> 4) << 4);  // ldmatrix B lane offset
    const int q2    = (lane & 3) * 2;
    const int t4    = (lane & 3) * 4;
    const int grow  = lane >> 2;

    const long stride = 8L * gridDim.x;

    for (long g = (long)blockIdx.x * 8 + wid; g < NSLAB; g += stride) {
        // ---- L2 prefetch of next slab ----
        {
            const long gp = g + stride;
            if (gp < NSLAB) {
                const char* px = (const char*)(x  + (size_t)gp * 2048) + lane * 256;
                const char* ph = (const char*)(hx + (size_t)gp * 2048) + lane * 256;
                pf_l2(px); pf_l2(px + 128);
                pf_l2(ph); pf_l2(ph + 128);
            }
        }

        // ---- A-fragments via LDG.128 (permuted K space) ----
        uint32_t xf[2][4][4], hf[2][4][4];
        {
            const float* xb = x  + (size_t)g * 2048;   // 32 rows x 64
            const float* hb = hx + (size_t)g * 2048;
            #pragma unroll
            for (int mb = 0; mb < 2; mb++) {
                const float* xr = xb + (mb * 16 + grow) * 64 + t4;
                const float* hr = hb + (mb * 16 + grow) * 64 + t4;
                #pragma unroll
                for (int kb = 0; kb < 4; kb++) {
                    float4 q0 = *(const float4*)(xr + kb * 16);
                    float4 q8 = *(const float4*)(xr + kb * 16 + 512);   // +8 rows
                    xf[mb][kb][0] = packh2(q0.x, q0.y);
                    xf[mb][kb][2] = packh2(q0.z, q0.w);
                    xf[mb][kb][1] = packh2(q8.x, q8.y);
                    xf[mb][kb][3] = packh2(q8.z, q8.w);
                    float4 p0 = *(const float4*)(hr + kb * 16);
                    float4 p8 = *(const float4*)(hr + kb * 16 + 512);
                    hf[mb][kb][0] = packh2(p0.x, p0.y);
                    hf[mb][kb][2] = packh2(p0.z, p0.w);
                    hf[mb][kb][1] = packh2(p8.x, p8.y);
                    hf[mb][kb][3] = packh2(p8.z, p8.w);
                }
            }
        }

        // ---- r = sig(x@Wir + hx@Whr + br) ----
        float rc[2][8][4];
        #pragma unroll
        for (int nb = 0; nb < 8; nb++) {
            float2 br = *(float2*)(sm + OFF_BIAS + (nb * 8 + q2) * 4);
            #pragma unroll
            for (int mb = 0; mb < 2; mb++) {
                rc[mb][nb][0] = br.x; rc[mb][nb][1] = br.y;
                rc[mb][nb][2] = br.x; rc[mb][nb][3] = br.y;
            }
        }
        gemm_gate(rc, xf, hf, SB + OFF_W, SB + OFF_W + 1 * 8192, laneB);

        // ---- rh = sigmoid(rc) * hx -> A-fragments (rc dies) ----
        uint32_t rhf[2][4][4];
        #pragma unroll
        for (int mb = 0; mb < 2; mb++) {
            #pragma unroll
            for (int kb = 0; kb < 4; kb++) {
                const float* ce = rc[mb][2 * kb];
                const float* co = rc[mb][2 * kb + 1];
                __half2 s0 = __floats2half2_rn(sigm(ce[0]), sigm(ce[1]));
                __half2 s1 = __floats2half2_rn(sigm(ce[2]), sigm(ce[3]));
                __half2 s2 = __floats2half2_rn(sigm(co[0]), sigm(co[1]));
                __half2 s3 = __floats2half2_rn(sigm(co[2]), sigm(co[3]));
                __half2 m0 = __hmul2(s0, *(const __half2*)&hf[mb][kb][0]);
                __half2 m1 = __hmul2(s1, *(const __half2*)&hf[mb][kb][1]);
                __half2 m2 = __hmul2(s2, *(const __half2*)&hf[mb][kb][2]);
                __half2 m3 = __hmul2(s3, *(const __half2*)&hf[mb][kb][3]);
                rhf[mb][kb][0] = *(uint32_t*)&m0;
                rhf[mb][kb][1] = *(uint32_t*)&m1;
                rhf[mb][kb][2] = *(uint32_t*)&m2;
                rhf[mb][kb][3] = *(uint32_t*)&m3;
            }
        }

        // ---- n = x@Win + rh@Whn + bn ----
        float nc[2][8][4];
        #pragma unroll
        for (int nb = 0; nb < 8; nb++) {
            float2 bn = *(float2*)(sm + OFF_BIAS + 512 + (nb * 8 + q2) * 4);
            #pragma unroll
            for (int mb = 0; mb < 2; mb++) {
                nc[mb][nb][0] = bn.x; nc[mb][nb][1] = bn.y;
                nc[mb][nb][2] = bn.x; nc[mb][nb][3] = bn.y;
            }
        }
        gemm_gate(nc, xf, rhf, SB + OFF_W + 4 * 8192, SB + OFF_W + 5 * 8192, laneB);

        // ---- z = sig(x@Wiz + hx@Whz + bz) (rhf dead) ----
        float zc[2][8][4];
        #pragma unroll
        for (int nb = 0; nb < 8; nb++) {
            float2 bz = *(float2*)(sm + OFF_BIAS + 256 + (nb * 8 + q2) * 4);
            #pragma unroll
            for (int mb = 0; mb < 2; mb++) {
                zc[mb][nb][0] = bz.x; zc[mb][nb][1] = bz.y;
                zc[mb][nb][2] = bz.x; zc[mb][nb][3] = bz.y;
            }
        }
        gemm_gate(zc, xf, hf, SB + OFF_W + 2 * 8192, SB + OFF_W + 3 * 8192, laneB);

        // ---- epilogue: h = hx + z*(n - hx); lane owns output cols
        //      kb*16+4t..+3 (sigma) -> STG.128; hx straight from hf ----
        #pragma unroll
        for (int mb = 0; mb < 2; mb++) {
            const long rg = g * 32 + mb * 16 + grow;
            #pragma unroll
            for (int kb = 0; kb < 4; kb++) {
                float2 h01 = __half22float2(*(const __half2*)&hf[mb][kb][0]); // row grow
                float2 h23 = __half22float2(*(const __half2*)&hf[mb][kb][2]);
                float2 g01 = __half22float2(*(const __half2*)&hf[mb][kb][1]); // row grow+8
                float2 g23 = __half22float2(*(const __half2*)&hf[mb][kb][3]);
                const float* ze = zc[mb][2 * kb];
                const float* zo = zc[mb][2 * kb + 1];
                const float* ne = nc[mb][2 * kb];
                const float* no = nc[mb][2 * kb + 1];
                float4 o0, o8;
                o0.x = fmaf(sigm(ze[0]), tanh_ap(ne[0]) - h01.x, h01.x);
                o0.y = fmaf(sigm(ze[1]), tanh_ap(ne[1]) - h01.y, h01.y);
                o0.z = fmaf(sigm(zo[0]), tanh_ap(no[0]) - h23.x, h23.x);
                o0.w = fmaf(sigm(zo[1]), tanh_ap(no[1]) - h23.y, h23.y);
                o8.x = fmaf(sigm(ze[2]), tanh_ap(ne[2]) - g01.x, g01.x);
                o8.y = fmaf(sigm(ze[3]), tanh_ap(ne[3]) - g01.y, g01.y);
                o8.z = fmaf(sigm(zo[2]), tanh_ap(no[2]) - g23.x, g23.x);
                o8.w = fmaf(sigm(zo[3]), tanh_ap(no[3]) - g23.y, g23.y);
                *(float4*)(out + rg * 64 + kb * 16 + t4)       = o0;
                *(float4*)(out + (rg + 8) * 64 + kb * 16 + t4) = o8;
            }
        }
    }
}

extern "C" void kernel_launch(void* const* d_in, const int* in_sizes, int n_in,
                              void* d_out, int out_size) {
    int sms = 0;
    cudaDeviceGetAttribute(&sms, cudaDevAttrMultiProcessorCount, 0);
    if (sms <= 0) sms = 148;
    cudaFuncSetAttribute(gru_kernel, cudaFuncAttributeMaxDynamicSharedMemorySize, SMEM_SZ);
    gru_kernel<<<sms, 256, SMEM_SZ>>>(
        (const float*)d_in[0], (const float*)d_in[1],
        (const float*)d_in[2], (const float*)d_in[3],
        (const float*)d_in[4], (const float*)d_in[5],
        (const float*)d_in[6], (const float*)d_in[7],
        (const float*)d_in[8], (const float*)d_in[9],
        (const float*)d_in[10], (float*)d_out);
}